// round 6
// baseline (speedup 1.0000x reference)
#include <cuda_runtime.h>
#include <cstdint>

// Chebyshev-KAN: out[b] = sum_d sum_{k=0..8} coeff[d*9+k] * T_k(x[b,d])
// x: (16384, 512) f32; coeff: (4608,) f32; out: (16384,) f32.
//
// R6: TMA-bulk (UBLKCP) pipeline. x streams to smem via cp.async.bulk with a
// 3-deep mbarrier pipeline (bypasses the per-thread L1tex queue that capped
// all LDG variants at ~3 TB/s). Coefficients: monomial-converted, packed
// f32x2, in registers. Compute reads x from smem (conflict-free LDS.64).
// Warp fold-tree reduces 16 row-partials in 31 shuffles.

#define DIM        512
#define NDEG       9
#define THREADS    256
#define ROWS_T     16
#define NTILES     1024                        // 16384 / 16
#define GRID       296                         // 2 CTAs per SM
#define NBUF       3
#define BUF_BYTES  (ROWS_T * DIM * 4)          // 32768
#define MBAR_OFF   (NBUF * BUF_BYTES)          // 98304
#define SPART_OFF  (MBAR_OFF + 64)
#define SPART_STRIDE 9                          // bank-conflict-free partials
#define SMEM_TOTAL (SPART_OFF + SPART_STRIDE * ROWS_T * 4 + 16)

typedef unsigned long long ull;

__device__ __forceinline__ ull pack2(float lo, float hi) {
    ull r; asm("mov.b64 %0, {%1, %2};" : "=l"(r) : "f"(lo), "f"(hi)); return r;
}
__device__ __forceinline__ void unpack2(ull v, float& lo, float& hi) {
    asm("mov.b64 {%0, %1}, %2;" : "=f"(lo), "=f"(hi) : "l"(v));
}
__device__ __forceinline__ ull fma2(ull a, ull b, ull c) {
    ull r; asm("fma.rn.f32x2 %0, %1, %2, %3;" : "=l"(r) : "l"(a), "l"(b), "l"(c)); return r;
}
__device__ __forceinline__ uint32_t su32(const void* p) {
    return (uint32_t)__cvta_generic_to_shared(p);
}
__device__ __forceinline__ void mbar_init(uint32_t mbar, uint32_t count) {
    asm volatile("mbarrier.init.shared.b64 [%0], %1;" :: "r"(mbar), "r"(count) : "memory");
}
__device__ __forceinline__ void mbar_expect_tx(uint32_t mbar, uint32_t bytes) {
    asm volatile("mbarrier.arrive.expect_tx.shared.b64 _, [%0], %1;"
                 :: "r"(mbar), "r"(bytes) : "memory");
}
__device__ __forceinline__ void mbar_wait(uint32_t mbar, uint32_t phase) {
    uint32_t done;
    do {
        asm volatile(
            "{\n\t.reg .pred p;\n\t"
            "mbarrier.try_wait.parity.acquire.cta.shared::cta.b64 p, [%1], %2, 0x989680;\n\t"
            "selp.b32 %0, 1, 0, p;\n\t}"
            : "=r"(done) : "r"(mbar), "r"(phase) : "memory");
    } while (!done);
}
__device__ __forceinline__ void bulk_g2s(uint32_t dst, const void* src,
                                         uint32_t bytes, uint32_t mbar) {
    asm volatile(
        "cp.async.bulk.shared::cluster.global.mbarrier::complete_tx::bytes "
        "[%0], [%1], %2, [%3];"
        :: "r"(dst), "l"(src), "r"(bytes), "r"(mbar) : "memory");
}

// Chebyshev coeffs c[0..8] -> monomial coeffs a[0..8].
__device__ __forceinline__ void cheb2mono(const float* __restrict__ c, float* a) {
    a[8] = 128.0f * c[8];
    a[7] =  64.0f * c[7];
    a[6] = fmaf(-256.0f, c[8], 32.0f * c[6]);
    a[5] = fmaf(-112.0f, c[7], 16.0f * c[5]);
    a[4] = fmaf(160.0f, c[8], fmaf(-48.0f, c[6], 8.0f * c[4]));
    a[3] = fmaf( 56.0f, c[7], fmaf(-20.0f, c[5], 4.0f * c[3]));
    a[2] = fmaf(-32.0f, c[8], fmaf(18.0f, c[6], fmaf(-8.0f, c[4], 2.0f * c[2])));
    a[1] = fmaf( -7.0f, c[7], fmaf( 5.0f, c[5], fmaf(-3.0f, c[3], c[1])));
    a[0] = ((c[0] - c[2]) + (c[4] - c[6])) + c[8];
}

__global__ __launch_bounds__(THREADS)
void kan_cheb_kernel(const float* __restrict__ x,
                     const float* __restrict__ coeff,
                     float* __restrict__ out)
{
    extern __shared__ __align__(128) char smem[];
    float* s_part = reinterpret_cast<float*>(smem + SPART_OFF);
    const uint32_t mb0 = su32(smem) + MBAR_OFF;

    const int tid  = threadIdx.x;
    const int lane = tid & 31;
    const int w    = tid >> 5;              // warp 0..7: dims [64w, 64w+64)
    const int d0   = w * 64 + lane * 2;

    // ---- prologue: 18 coeffs -> monomial -> 9 packed f32x2 registers ----
    float cf[18];
    {
        const float2* c2 = reinterpret_cast<const float2*>(coeff + d0 * NDEG);
        #pragma unroll
        for (int i = 0; i < 9; ++i) { float2 v = c2[i]; cf[2*i] = v.x; cf[2*i+1] = v.y; }
    }
    ull A[9];
    {
        float t0[9], t1[9];
        cheb2mono(cf, t0); cheb2mono(cf + 9, t1);
        #pragma unroll
        for (int k = 0; k < 9; ++k) A[k] = pack2(t0[k], t1[k]);
    }

    // ---- mbarrier init + initial TMA issues (3-deep) ----
    if (tid == 0) {
        #pragma unroll
        for (int b = 0; b < NBUF; ++b) mbar_init(mb0 + 8u * b, 1u);
    }
    __syncthreads();
    if (tid == 0) {
        #pragma unroll
        for (int b = 0; b < NBUF; ++b) {
            int t = blockIdx.x + b * GRID;
            if (t < NTILES) {
                mbar_expect_tx(mb0 + 8u * b, BUF_BYTES);
                bulk_g2s(su32(smem) + b * BUF_BYTES,
                         x + (size_t)t * (ROWS_T * DIM), BUF_BYTES, mb0 + 8u * b);
            }
        }
    }

    // row index this lane's fold result corresponds to (lanes with bit0==0 store)
    const int frow = ((lane >> 1) & 1) * 8 + ((lane >> 2) & 1) * 4
                   + ((lane >> 3) & 1) * 2 + ((lane >> 4) & 1);

    int it = 0;
    for (int t = blockIdx.x; t < NTILES; t += GRID, ++it) {
        const int b = it % NBUF;
        const uint32_t ph = (uint32_t)((it / NBUF) & 1);
        mbar_wait(mb0 + 8u * b, ph);

        const float2* xs = reinterpret_cast<const float2*>(smem + b * BUF_BYTES);
        const int base2 = w * 32 + lane;        // float2 col within row

        float acc[ROWS_T];
        #pragma unroll
        for (int r = 0; r < ROWS_T; ++r) {
            float2 v = xs[r * (DIM / 2) + base2];
            ull p = A[8];
            ull xp = pack2(v.x, v.y);
            #pragma unroll
            for (int k = 7; k >= 0; --k) p = fma2(p, xp, A[k]);
            float lo, hi; unpack2(p, lo, hi);
            acc[r] = lo + hi;
        }

        // ---- fold-tree: 16 reductions in 31 shuffles; lane->row bijection ----
        float v8[8];
        #pragma unroll
        for (int i = 0; i < 8; ++i) {
            float lo = acc[2*i]   + __shfl_xor_sync(0xffffffffu, acc[2*i],   16);
            float hi = acc[2*i+1] + __shfl_xor_sync(0xffffffffu, acc[2*i+1], 16);
            v8[i] = (lane & 16) ? hi : lo;
        }
        float v4[4];
        #pragma unroll
        for (int i = 0; i < 4; ++i) {
            float lo = v8[2*i]   + __shfl_xor_sync(0xffffffffu, v8[2*i],   8);
            float hi = v8[2*i+1] + __shfl_xor_sync(0xffffffffu, v8[2*i+1], 8);
            v4[i] = (lane & 8) ? hi : lo;
        }
        float v2[2];
        #pragma unroll
        for (int i = 0; i < 2; ++i) {
            float lo = v4[2*i]   + __shfl_xor_sync(0xffffffffu, v4[2*i],   4);
            float hi = v4[2*i+1] + __shfl_xor_sync(0xffffffffu, v4[2*i+1], 4);
            v2[i] = (lane & 4) ? hi : lo;
        }
        float v1;
        {
            float lo = v2[0] + __shfl_xor_sync(0xffffffffu, v2[0], 2);
            float hi = v2[1] + __shfl_xor_sync(0xffffffffu, v2[1], 2);
            v1 = (lane & 2) ? hi : lo;
        }
        float tot = v1 + __shfl_xor_sync(0xffffffffu, v1, 1);

        if (!(lane & 1)) s_part[SPART_STRIDE * frow + w] = tot;
        __syncthreads();

        // buffer b fully consumed -> reissue TMA into it
        if (tid == 0) {
            int tn = t + NBUF * GRID;
            if (tn < NTILES) {
                mbar_expect_tx(mb0 + 8u * b, BUF_BYTES);
                bulk_g2s(su32(smem) + b * BUF_BYTES,
                         x + (size_t)tn * (ROWS_T * DIM), BUF_BYTES, mb0 + 8u * b);
            }
        }

        if (tid < ROWS_T) {
            const float* p = &s_part[SPART_STRIDE * tid];
            float s = ((p[0] + p[1]) + (p[2] + p[3])) + ((p[4] + p[5]) + (p[6] + p[7]));
            out[t * ROWS_T + tid] = s;
        }
        __syncthreads();   // protect s_part before next tile's stores
    }
}

extern "C" void kernel_launch(void* const* d_in, const int* in_sizes, int n_in,
                              void* d_out, int out_size)
{
    const float* x     = (const float*)d_in[0];
    const float* coeff = (const float*)d_in[1];
    // d_in[2] = degree (int32, fixed at 8) — baked in at compile time.
    float* out = (float*)d_out;

    cudaFuncSetAttribute(kan_cheb_kernel,
                         cudaFuncAttributeMaxDynamicSharedMemorySize, SMEM_TOTAL);
    kan_cheb_kernel<<<GRID, THREADS, SMEM_TOTAL>>>(x, coeff, out);
}

// round 7
// speedup vs baseline: 1.1629x; 1.1629x over previous
#include <cuda_runtime.h>
#include <cstdint>

// Chebyshev-KAN: out[b] = sum_d sum_{k=0..8} coeff[d*9+k] * T_k(x[b,d])
// x: (16384, 512) f32; coeff: (4608,) f32; out: (16384,) f32.
//
// R7: warp-autonomous, sync-free. k1: each warp owns a 64-dim slice
// (monomial coeffs in 9 packed-f32x2 regs) and grid-strides over 4-row
// groups, double-buffered LDG.64, fold-tree reduction (9 shuffles for 4
// rows), writes per-slice partials to __device__ scratch. No syncthreads,
// no atomics, one wave (grid=592, 4 CTAs/SM). k2: coalesced 8->1 reduce.

#define DIM      512
#define NDEG     9
#define THREADS  256
#define TILE     4
#define NGROUPS  4096          // 16384 / 4
#define GRID1    592           // 148 SMs x 4 CTAs, single wave
#define NROWS    16384

typedef unsigned long long ull;

__device__ float g_partial[8][NROWS];   // 512 KB scratch (static, no alloc)

__device__ __forceinline__ ull pack2(float lo, float hi) {
    ull r; asm("mov.b64 %0, {%1, %2};" : "=l"(r) : "f"(lo), "f"(hi)); return r;
}
__device__ __forceinline__ void unpack2(ull v, float& lo, float& hi) {
    asm("mov.b64 {%0, %1}, %2;" : "=f"(lo), "=f"(hi) : "l"(v));
}
__device__ __forceinline__ ull fma2(ull a, ull b, ull c) {
    ull r; asm("fma.rn.f32x2 %0, %1, %2, %3;" : "=l"(r) : "l"(a), "l"(b), "l"(c)); return r;
}

// Chebyshev coeffs c[0..8] -> monomial coeffs a[0..8].
__device__ __forceinline__ void cheb2mono(const float* __restrict__ c, float* a) {
    a[8] = 128.0f * c[8];
    a[7] =  64.0f * c[7];
    a[6] = fmaf(-256.0f, c[8], 32.0f * c[6]);
    a[5] = fmaf(-112.0f, c[7], 16.0f * c[5]);
    a[4] = fmaf(160.0f, c[8], fmaf(-48.0f, c[6], 8.0f * c[4]));
    a[3] = fmaf( 56.0f, c[7], fmaf(-20.0f, c[5], 4.0f * c[3]));
    a[2] = fmaf(-32.0f, c[8], fmaf(18.0f, c[6], fmaf(-8.0f, c[4], 2.0f * c[2])));
    a[1] = fmaf( -7.0f, c[7], fmaf( 5.0f, c[5], fmaf(-3.0f, c[3], c[1])));
    a[0] = ((c[0] - c[2]) + (c[4] - c[6])) + c[8];
}

__device__ __forceinline__ void load_group(const float2* __restrict__ x2,
                                           int g, int col2, float2* xb) {
    const float2* p = x2 + (size_t)(TILE * g) * (DIM / 2) + col2;
    #pragma unroll
    for (int r = 0; r < TILE; ++r)
        xb[r] = p[r * (DIM / 2)];
}

// Compute 4 rows, fold, store partials for slice s at rows [4g, 4g+4).
__device__ __forceinline__ void do_group(const float2* xb, const ull* A,
                                         int s, int g, int lane) {
    float acc[TILE];
    #pragma unroll
    for (int r = 0; r < TILE; ++r) {
        ull xp = pack2(xb[r].x, xb[r].y);
        ull p = A[8];
        #pragma unroll
        for (int k = 7; k >= 0; --k) p = fma2(p, xp, A[k]);
        float lo, hi; unpack2(p, lo, hi);
        acc[r] = lo + hi;
    }
    // fold tree: 9 shuffles reduce 4 rows; lane group (bits 3,4) -> row
    float v0, v1;
    {
        float lo = acc[0] + __shfl_xor_sync(0xffffffffu, acc[0], 16);
        float hi = acc[1] + __shfl_xor_sync(0xffffffffu, acc[1], 16);
        v0 = (lane & 16) ? hi : lo;
        lo = acc[2] + __shfl_xor_sync(0xffffffffu, acc[2], 16);
        hi = acc[3] + __shfl_xor_sync(0xffffffffu, acc[3], 16);
        v1 = (lane & 16) ? hi : lo;
    }
    float u;
    {
        float lo = v0 + __shfl_xor_sync(0xffffffffu, v0, 8);
        float hi = v1 + __shfl_xor_sync(0xffffffffu, v1, 8);
        u = (lane & 8) ? hi : lo;
    }
    u += __shfl_xor_sync(0xffffffffu, u, 4);
    u += __shfl_xor_sync(0xffffffffu, u, 2);
    u += __shfl_xor_sync(0xffffffffu, u, 1);
    // lane 0 -> row 0, lane 8 -> row 2, lane 16 -> row 1, lane 24 -> row 3
    if ((lane & 7) == 0) {
        int rm = 2 * ((lane >> 3) & 1) + ((lane >> 4) & 1);
        g_partial[s][TILE * g + rm] = u;
    }
}

__global__ __launch_bounds__(THREADS, 4)
void kan_cheb_partial(const float* __restrict__ x,
                      const float* __restrict__ coeff)
{
    const int tid  = threadIdx.x;
    const int lane = tid & 31;
    const int s    = tid >> 5;            // slice 0..7 (fixed per warp)
    const int d0   = s * 64 + lane * 2;
    const int col2 = d0 >> 1;

    const float2* x2 = reinterpret_cast<const float2*>(x);

    // issue first x loads BEFORE coefficient work (independent)
    int g = blockIdx.x;
    float2 xa[TILE], xb[TILE];
    load_group(x2, g, col2, xa);

    // coeff prologue: 18 consecutive floats -> monomial -> packed regs
    float cf[18];
    {
        const float2* c2 = reinterpret_cast<const float2*>(coeff + d0 * NDEG);
        #pragma unroll
        for (int i = 0; i < 9; ++i) { float2 v = c2[i]; cf[2*i] = v.x; cf[2*i+1] = v.y; }
    }
    ull A[9];
    {
        float t0[9], t1[9];
        cheb2mono(cf, t0); cheb2mono(cf + 9, t1);
        #pragma unroll
        for (int k = 0; k < 9; ++k) A[k] = pack2(t0[k], t1[k]);
    }

    // warp-autonomous grid-stride loop, register double buffer
    for (;;) {
        int gn = g + GRID1;
        if (gn < NGROUPS) load_group(x2, gn, col2, xb);
        do_group(xa, A, s, g, lane);
        if (gn >= NGROUPS) break;
        g = gn;

        gn = g + GRID1;
        if (gn < NGROUPS) load_group(x2, gn, col2, xa);
        do_group(xb, A, s, g, lane);
        if (gn >= NGROUPS) break;
        g = gn;
    }
}

__global__ __launch_bounds__(512)
void kan_cheb_reduce(float* __restrict__ out)
{
    const int row = blockIdx.x * 512 + threadIdx.x;
    float sum = 0.0f;
    #pragma unroll
    for (int i = 0; i < 8; ++i)
        sum += g_partial[i][row];
    out[row] = sum;
}

extern "C" void kernel_launch(void* const* d_in, const int* in_sizes, int n_in,
                              void* d_out, int out_size)
{
    const float* x     = (const float*)d_in[0];
    const float* coeff = (const float*)d_in[1];
    // d_in[2] = degree (int32, fixed at 8) — baked in at compile time.
    float* out = (float*)d_out;

    kan_cheb_partial<<<GRID1, THREADS>>>(x, coeff);
    kan_cheb_reduce<<<NROWS / 512, 512>>>(out);
}

// round 8
// speedup vs baseline: 1.3851x; 1.1910x over previous
#include <cuda_runtime.h>
#include <cstdint>

// Chebyshev-KAN: out[b] = sum_d sum_{k=0..8} coeff[d*9+k] * T_k(x[b,d])
// x: (16384, 512) f32; coeff: (4608,) f32; out: (16384,) f32.
//
// R8: warp-autonomous + REDG epilogue. kernel0 zeroes out (64KB). k1: warp =
// 64-dim slice, monomial coeffs in 9 packed-f32x2 regs, grid-strides over
// 8-row groups with register double buffering (8 LDG.64 in flight), fold-tree
// reduction (16 shuffles / 8 rows), then red.global.add.f32 of the slice
// partial straight into out[] (no scratch, no reduce kernel). No syncthreads,
// single wave (grid=592).

#define DIM      512
#define NDEG     9
#define THREADS  256
#define TILE     8
#define NGROUPS  2048          // 16384 / 8
#define GRID1    592           // 148 SMs x 4 CTAs (grid-stride; ~3.5 groups/CTA)
#define NROWS    16384

typedef unsigned long long ull;

__device__ __forceinline__ ull pack2(float lo, float hi) {
    ull r; asm("mov.b64 %0, {%1, %2};" : "=l"(r) : "f"(lo), "f"(hi)); return r;
}
__device__ __forceinline__ void unpack2(ull v, float& lo, float& hi) {
    asm("mov.b64 {%0, %1}, %2;" : "=f"(lo), "=f"(hi) : "l"(v));
}
__device__ __forceinline__ ull fma2(ull a, ull b, ull c) {
    ull r; asm("fma.rn.f32x2 %0, %1, %2, %3;" : "=l"(r) : "l"(a), "l"(b), "l"(c)); return r;
}

// Chebyshev coeffs c[0..8] -> monomial coeffs a[0..8].
__device__ __forceinline__ void cheb2mono(const float* __restrict__ c, float* a) {
    a[8] = 128.0f * c[8];
    a[7] =  64.0f * c[7];
    a[6] = fmaf(-256.0f, c[8], 32.0f * c[6]);
    a[5] = fmaf(-112.0f, c[7], 16.0f * c[5]);
    a[4] = fmaf(160.0f, c[8], fmaf(-48.0f, c[6], 8.0f * c[4]));
    a[3] = fmaf( 56.0f, c[7], fmaf(-20.0f, c[5], 4.0f * c[3]));
    a[2] = fmaf(-32.0f, c[8], fmaf(18.0f, c[6], fmaf(-8.0f, c[4], 2.0f * c[2])));
    a[1] = fmaf( -7.0f, c[7], fmaf( 5.0f, c[5], fmaf(-3.0f, c[3], c[1])));
    a[0] = ((c[0] - c[2]) + (c[4] - c[6])) + c[8];
}

__device__ __forceinline__ void load_group(const float2* __restrict__ x2,
                                           int g, int col2, float2* xb) {
    const float2* p = x2 + (size_t)(TILE * g) * (DIM / 2) + col2;
    #pragma unroll
    for (int r = 0; r < TILE; ++r)
        xb[r] = p[r * (DIM / 2)];
}

// Compute 8 rows of this warp's 64-dim slice, fold, REDG into out[8g..8g+8).
__device__ __forceinline__ void do_group(const float2* xb, const ull* A,
                                         float* __restrict__ out,
                                         int g, int lane) {
    float acc[TILE];
    #pragma unroll
    for (int r = 0; r < TILE; ++r) {
        ull xp = pack2(xb[r].x, xb[r].y);
        ull p = A[8];
        #pragma unroll
        for (int k = 7; k >= 0; --k) p = fma2(p, xp, A[k]);
        float lo, hi; unpack2(p, lo, hi);
        acc[r] = lo + hi;
    }

    // fold tree: 8 values -> 1 per lane-octant. Row index bits:
    // bit0=(lane>>4)&1 (mask16 fold), bit1=(lane>>3)&1 (mask8), bit2=(lane>>2)&1 (mask4)
    float v4[4];
    #pragma unroll
    for (int i = 0; i < 4; ++i) {
        float lo = acc[2*i]   + __shfl_xor_sync(0xffffffffu, acc[2*i],   16);
        float hi = acc[2*i+1] + __shfl_xor_sync(0xffffffffu, acc[2*i+1], 16);
        v4[i] = (lane & 16) ? hi : lo;
    }
    float v2[2];
    #pragma unroll
    for (int i = 0; i < 2; ++i) {
        float lo = v4[2*i]   + __shfl_xor_sync(0xffffffffu, v4[2*i],   8);
        float hi = v4[2*i+1] + __shfl_xor_sync(0xffffffffu, v4[2*i+1], 8);
        v2[i] = (lane & 8) ? hi : lo;
    }
    float u;
    {
        float lo = v2[0] + __shfl_xor_sync(0xffffffffu, v2[0], 4);
        float hi = v2[1] + __shfl_xor_sync(0xffffffffu, v2[1], 4);
        u = (lane & 4) ? hi : lo;
    }
    u += __shfl_xor_sync(0xffffffffu, u, 2);
    u += __shfl_xor_sync(0xffffffffu, u, 1);

    if ((lane & 3) == 0) {
        int rm = ((lane >> 4) & 1) | (((lane >> 3) & 1) << 1) | (((lane >> 2) & 1) << 2);
        atomicAdd(&out[TILE * g + rm], u);   // RED.E.ADD.F32 (no return)
    }
}

__global__ __launch_bounds__(THREADS, 3)
void kan_cheb_partial(const float* __restrict__ x,
                      const float* __restrict__ coeff,
                      float* __restrict__ out)
{
    const int tid  = threadIdx.x;
    const int lane = tid & 31;
    const int s    = tid >> 5;            // slice 0..7 (fixed per warp)
    const int d0   = s * 64 + lane * 2;
    const int col2 = d0 >> 1;

    const float2* x2 = reinterpret_cast<const float2*>(x);

    // issue first x loads BEFORE coefficient work (independent)
    int g = blockIdx.x;
    float2 xa[TILE], xb[TILE];
    load_group(x2, g, col2, xa);

    // coeff prologue: 18 consecutive floats -> monomial -> packed regs
    float cf[18];
    {
        const float2* c2 = reinterpret_cast<const float2*>(coeff + d0 * NDEG);
        #pragma unroll
        for (int i = 0; i < 9; ++i) { float2 v = c2[i]; cf[2*i] = v.x; cf[2*i+1] = v.y; }
    }
    ull A[9];
    {
        float t0[9], t1[9];
        cheb2mono(cf, t0); cheb2mono(cf + 9, t1);
        #pragma unroll
        for (int k = 0; k < 9; ++k) A[k] = pack2(t0[k], t1[k]);
    }

    // warp-autonomous grid-stride loop, register double buffer
    for (;;) {
        int gn = g + GRID1;
        if (gn < NGROUPS) load_group(x2, gn, col2, xb);
        do_group(xa, A, out, g, lane);
        if (gn >= NGROUPS) break;
        g = gn;

        gn = g + GRID1;
        if (gn < NGROUPS) load_group(x2, gn, col2, xa);
        do_group(xb, A, out, g, lane);
        if (gn >= NGROUPS) break;
        g = gn;
    }
}

__global__ __launch_bounds__(256)
void kan_zero_out(float4* __restrict__ out4)
{
    out4[blockIdx.x * 256 + threadIdx.x] = make_float4(0.f, 0.f, 0.f, 0.f);
}

extern "C" void kernel_launch(void* const* d_in, const int* in_sizes, int n_in,
                              void* d_out, int out_size)
{
    const float* x     = (const float*)d_in[0];
    const float* coeff = (const float*)d_in[1];
    // d_in[2] = degree (int32, fixed at 8) — baked in at compile time.
    float* out = (float*)d_out;

    kan_zero_out<<<NROWS / 4 / 256, 256>>>((float4*)out);
    kan_cheb_partial<<<GRID1, THREADS>>>(x, coeff, out);
}